// round 15
// baseline (speedup 1.0000x reference)
#include <cuda_runtime.h>

// B=16 images of 512x512, 50 Jacobi iters of masked 5-pt stencil.
// 5 kernels x 10 fused steps, state in registers.
// CTA = 64 out rows x 512 cols (84 loaded rows); 384 thr = 32 lanes x 12 slabs x 7 rows.
// Warp owns a full row (horiz neighbors = regs/shuffle). Vertical slab exchange via
// parity-double-buffered smem, ONE bar per step. Masked update = bitwise select.

#define NB    16
#define NRES  512
#define NPTS  (NB * NRES * NRES)
#define NGRP  (NPTS / 4)

#define KFUSE   10
#define TROWS   64
#define LROWS   (TROWS + 2 * KFUSE)   // 84
#define NTY     12
#define RPT     7                     // NTY*RPT = 84
#define THREADS (NTY * 32)            // 384
#define NTILES  (NRES / TROWS)        // 8
#define SB_BYTES (2 * 2 * 4 * THREADS * 16)   // 98304

__device__ float         g_u0[NPTS];
__device__ float         g_u1[NPTS];
__device__ unsigned char g_m[NGRP];   // bit j of byte g = fluid(point 4g+j)
__device__ float         g_base[NPTS];

__global__ __launch_bounds__(256) void setup_kernel(
        const float4* __restrict__ xmix,
        const float*  __restrict__ w_back,
        const float*  __restrict__ b_back,
        const float*  __restrict__ logit,
        const float*  __restrict__ y_mean,
        const float*  __restrict__ y_std) {
    int g = blockIdx.x * blockDim.x + threadIdx.x;
    if (g >= NGRP) return;
    int xg  = g & 127;
    int row = g >> 7;
    int y   = row & (NRES - 1);
    int x0  = xg * 4;

    float rs  = 0.25f / (1.0f + __expf(-logit[0]));
    float inv = 1.0f / (y_std[0] + 1e-5f);
    float ofs = -y_mean[0] * inv;
    float w0  = w_back[0], w1 = w_back[1], bb = b_back[0];
    float ys  = (float)y * (1.0f / 511.0f);
    float wy  = fminf(ys, 1.0f - ys);

    float4 u0, base;
    float* up = &u0.x;
    float* bp = &base.x;
    unsigned mask = 0;
    #pragma unroll
    for (int i = 0; i < 4; i++) {
        int x = x0 + i;
        float4 xm = xmix[g * 4 + i];             // [x0, x1, geom, bc]
        bool solid = xm.z > 0.5f;
        bool edge  = (x == 0) | (x == NRES - 1) | (y == 0) | (y == NRES - 1);
        bool dir   = edge | solid;
        up[i] = dir ? xm.w : 0.0f;
        if (!dir) mask |= (1u << i);

        float xs = (float)x * (1.0f / 511.0f);
        float d  = fminf(wy, fminf(xs, 1.0f - xs));
        float w  = fminf(fmaxf(d * 20.0f, 0.0f), 1.0f);
        if (solid) w = 0.0f;
        float r = fmaf(xm.x, w0, fmaf(xm.y, w1, bb));
        bp[i] = fmaf(w * rs, r, ofs);
    }
    ((float4*)g_u0)[g]   = u0;
    ((float4*)g_base)[g] = base;
    g_m[g] = (unsigned char)mask;
}

// bitwise masked select: fluid -> fl, dirichlet -> ol (k compile-time)
__device__ __forceinline__ float msel(float fl, float ol, unsigned m, int k) {
    int M = ((int)(m << (31 - k))) >> 31;
    return __int_as_float((__float_as_int(fl) & M) | (__float_as_int(ol) & ~M));
}

// packed: o = (h + (u + d)) * 0.25   for two lanes at once (bit-identical to scalar)
__device__ __forceinline__ void pquad(float& ox, float& oy,
        float hx, float hy, float ux, float uy, float dx, float dy) {
    asm("{\n\t"
        ".reg .b64 h,u,d,t,q;\n\t"
        "mov.b64 q, 0x3E8000003E800000;\n\t"
        "mov.b64 h,{%2,%3};\n\t"
        "mov.b64 u,{%4,%5};\n\t"
        "mov.b64 d,{%6,%7};\n\t"
        "add.rn.f32x2 t,u,d;\n\t"
        "add.rn.f32x2 t,h,t;\n\t"
        "mul.rn.f32x2 t,t,q;\n\t"
        "mov.b64 {%0,%1},t;\n\t"
        "}"
        : "=f"(ox), "=f"(oy)
        : "f"(hx), "f"(hy), "f"(ux), "f"(uy), "f"(dx), "f"(dy));
}

// one float4 group update; gi = group index within thread (compile-time)
__device__ __forceinline__ float4 upd4(float4 c, float4 U, float4 D,
                                       float L, float R, unsigned m, int gi) {
    float h0 = L   + c.y;
    float h1 = c.x + c.z;
    float h2 = c.y + c.w;
    float h3 = c.z + R;
    float f0, f1, f2, f3;
    pquad(f0, f1, h0, h1, U.x, U.y, D.x, D.y);
    pquad(f2, f3, h2, h3, U.z, U.w, D.z, D.w);
    float4 o;
    o.x = msel(f0, c.x, m, gi * 8 + 0);
    o.y = msel(f1, c.y, m, gi * 8 + 1);
    o.z = msel(f2, c.z, m, gi * 8 + 2);
    o.w = msel(f3, c.w, m, gi * 8 + 3);
    return o;
}

// sb layout: [parity][top/bot][f4 idx][thread]
#define SBI(p, tb, i, t) ((((p) * 2 + (tb)) * 4 + (i)) * THREADS + (t))

template <bool FINAL>
__global__ __launch_bounds__(THREADS, 1) void jacobi10_kernel(
        int parity, float* __restrict__ outp, const float* __restrict__ y_std) {
    const float4* __restrict__ src = parity ? (const float4*)g_u1 : (const float4*)g_u0;
    float4*       __restrict__ dst = parity ? (float4*)g_u0       : (float4*)g_u1;
    extern __shared__ float4 sb[];

    int tid  = threadIdx.x;
    int lane = tid & 31;
    int ty   = tid >> 5;
    int img  = blockIdx.x >> 3;
    int tile = blockIdx.x & (NTILES - 1);
    int lr0  = tile * TROWS - KFUSE;

    // ---- load 7 rows x 4 float4 + mask words (row-clamped; clamped rows all-Dirichlet)
    float4   v[RPT][4];
    unsigned mrow[RPT];
    #pragma unroll
    for (int r = 0; r < RPT; r++) {
        int lr = lr0 + ty * RPT + r;
        lr = min(max(lr, 0), NRES - 1);
        int grow = img * NRES + lr;
        int gi   = grow * 128 + lane * 4;
        v[r][0] = src[gi + 0];
        v[r][1] = src[gi + 1];
        v[r][2] = src[gi + 2];
        v[r][3] = src[gi + 3];
        mrow[r] = *reinterpret_cast<const unsigned*>(g_m + (size_t)grow * 128 + lane * 4);
    }

    // ---- prologue: publish old boundary rows into parity-0 buffer
    #pragma unroll
    for (int i = 0; i < 4; i++) {
        sb[SBI(0, 0, i, tid)] = v[0][i];         // top of slab
        sb[SBI(0, 1, i, tid)] = v[RPT - 1][i];   // bottom of slab
    }
    __syncthreads();

    // ---- 10 fused steps, ONE bar per step
    for (int s = 0; s < KFUSE; s++) {
        int cur = s & 1;
        int nxt = cur ^ 1;

        // rolling "previous old row" = above neighbor
        float4 p0, p1, p2, p3;
        if (ty == 0) { p0 = v[0][0]; p1 = v[0][1]; p2 = v[0][2]; p3 = v[0][3]; }
        else {
            p0 = sb[SBI(cur, 1, 0, tid - 32)];
            p1 = sb[SBI(cur, 1, 1, tid - 32)];
            p2 = sb[SBI(cur, 1, 2, tid - 32)];
            p3 = sb[SBI(cur, 1, 3, tid - 32)];
        }

        #pragma unroll
        for (int r = 0; r < RPT; r++) {
            float4 d0, d1, d2, d3;
            if (r < RPT - 1) { d0 = v[r+1][0]; d1 = v[r+1][1]; d2 = v[r+1][2]; d3 = v[r+1][3]; }
            else if (ty == NTY - 1) { d0 = v[r][0]; d1 = v[r][1]; d2 = v[r][2]; d3 = v[r][3]; }
            else {
                d0 = sb[SBI(cur, 0, 0, tid + 32)];
                d1 = sb[SBI(cur, 0, 1, tid + 32)];
                d2 = sb[SBI(cur, 0, 2, tid + 32)];
                d3 = sb[SBI(cur, 0, 3, tid + 32)];
            }

            float le = __shfl_up_sync(0xFFFFFFFFu, v[r][3].w, 1);   // lane0 edge = Dirichlet
            float ri = __shfl_down_sync(0xFFFFFFFFu, v[r][0].x, 1); // lane31 edge

            unsigned m = mrow[r];
            float4 n0 = upd4(v[r][0], p0, d0, le,        v[r][1].x, m, 0);
            float4 n1 = upd4(v[r][1], p1, d1, v[r][0].w, v[r][2].x, m, 1);
            float4 n2 = upd4(v[r][2], p2, d2, v[r][1].w, v[r][3].x, m, 2);
            float4 n3 = upd4(v[r][3], p3, d3, v[r][2].w, ri,        m, 3);

            p0 = v[r][0]; p1 = v[r][1]; p2 = v[r][2]; p3 = v[r][3];
            v[r][0] = n0; v[r][1] = n1; v[r][2] = n2; v[r][3] = n3;

            if (r == 0) {                    // publish NEW top for next step
                sb[SBI(nxt, 0, 0, tid)] = n0;
                sb[SBI(nxt, 0, 1, tid)] = n1;
                sb[SBI(nxt, 0, 2, tid)] = n2;
                sb[SBI(nxt, 0, 3, tid)] = n3;
            }
            if (r == RPT - 1) {              // publish NEW bottom for next step
                sb[SBI(nxt, 1, 0, tid)] = n0;
                sb[SBI(nxt, 1, 1, tid)] = n1;
                sb[SBI(nxt, 1, 2, tid)] = n2;
                sb[SBI(nxt, 1, 3, tid)] = n3;
            }
        }
        __syncthreads();
    }

    // ---- store valid interior rows (local [KFUSE, KFUSE+TROWS))
    float inv = 0.0f;
    if (FINAL) inv = 1.0f / (__ldg(y_std) + 1e-5f);
    #pragma unroll
    for (int r = 0; r < RPT; r++) {
        int lrl = ty * RPT + r;
        if (lrl >= KFUSE && lrl < KFUSE + TROWS) {
            int grow = img * NRES + lr0 + lrl;
            int gi   = grow * 128 + lane * 4;
            if (FINAL) {
                const float4* b4 = (const float4*)g_base;
                float4* o4 = (float4*)outp;
                #pragma unroll
                for (int i = 0; i < 4; i++) {
                    float4 b = b4[gi + i];
                    float4 u = v[r][i];
                    float4 o;
                    o.x = fmaf(u.x, inv, b.x);
                    o.y = fmaf(u.y, inv, b.y);
                    o.z = fmaf(u.z, inv, b.z);
                    o.w = fmaf(u.w, inv, b.w);
                    o4[gi + i] = o;
                }
            } else {
                dst[gi + 0] = v[r][0];
                dst[gi + 1] = v[r][1];
                dst[gi + 2] = v[r][2];
                dst[gi + 3] = v[r][3];
            }
        }
    }
}

extern "C" void kernel_launch(void* const* d_in, const int* in_sizes, int n_in,
                              void* d_out, int out_size) {
    const float4* xmix   = (const float4*)d_in[0];
    const float*  w_back = (const float*)d_in[1];
    const float*  b_back = (const float*)d_in[2];
    const float*  logit  = (const float*)d_in[3];
    const float*  y_mean = (const float*)d_in[4];
    const float*  y_std  = (const float*)d_in[5];

    // Idempotent, not stream-ordered; called unconditionally (no static guards).
    cudaFuncSetAttribute(jacobi10_kernel<false>,
                         cudaFuncAttributeMaxDynamicSharedMemorySize, SB_BYTES);
    cudaFuncSetAttribute(jacobi10_kernel<true>,
                         cudaFuncAttributeMaxDynamicSharedMemorySize, SB_BYTES);

    setup_kernel<<<NGRP / 256, 256>>>(xmix, w_back, b_back, logit, y_mean, y_std);

    for (int s = 0; s < 4; s++)
        jacobi10_kernel<false><<<NB * NTILES, THREADS, SB_BYTES>>>(s & 1, nullptr, nullptr);
    jacobi10_kernel<true><<<NB * NTILES, THREADS, SB_BYTES>>>(0, (float*)d_out, y_std);
}